// round 16
// baseline (speedup 1.0000x reference)
#include <cuda_runtime.h>
#include <cuda.h>
#include <cuda_bf16.h>
#include <cstdint>
#include <math.h>

#define BATCH 4
#define SEQ   1024
#define DIMC  768
#define NH    12
#define HD    64
#define RK    8
#define MTOT  (BATCH*SEQ)     /* 4096 */
#define BH    (BATCH*NH)      /* 48   */
#define KDIM  768
#define PER   (DIMC*DIMC)

// ---------------- scratch (device globals; no allocation allowed) ----------
__device__ __align__(16) float g_qkv[3*MTOT*DIMC];     // q,k,v planes
__device__ __align__(16) __nv_bfloat16 g_lqp[BH*SEQ*16]; // [hi8|lo8] scaled
__device__ __align__(16) __nv_bfloat16 g_lkp[BH*SEQ*16];
__device__ __align__(16) float g_lq2[BH*SEQ];
__device__ __align__(16) float g_lk2[BH*SEQ];
__device__ __align__(16) float g_sv [BH*HD];
__device__ float g_klpart[256];
__device__ __align__(1024) __nv_bfloat16 g_xh [MTOT*DIMC];
__device__ __align__(1024) __nv_bfloat16 g_xl [MTOT*DIMC];
__device__ __align__(1024) __nv_bfloat16 g_wh [3*PER];
__device__ __align__(1024) __nv_bfloat16 g_wl [3*PER];
__device__ __align__(1024) __nv_bfloat16 g_woh[PER];
__device__ __align__(1024) __nv_bfloat16 g_wol[PER];
__device__ __align__(1024) __nv_bfloat16 g_ch [MTOT*DIMC];
__device__ __align__(1024) __nv_bfloat16 g_cl [MTOT*DIMC];

// ---------------- fast approx helpers --------------------------------------
__device__ __forceinline__ float ex2a(float x) {
    float y; asm("ex2.approx.f32 %0, %1;" : "=f"(y) : "f"(x)); return y;
}
__device__ __forceinline__ float sqa(float x) {
    float y; asm("sqrt.approx.f32 %0, %1;" : "=f"(y) : "f"(x)); return y;
}
__device__ __forceinline__ uint32_t pack_bf16x2(float lo, float hi) {
    uint32_t r;
    asm("cvt.rn.bf16x2.f32 %0, %1, %2;" : "=r"(r) : "f"(hi), "f"(lo));
    return r;
}

// ---------------- smem / mma primitives -------------------------------------
__device__ __forceinline__ uint32_t smem_u32(const void* p) {
    uint32_t a;
    asm("{ .reg .u64 t; cvta.to.shared.u64 t, %1; cvt.u32.u64 %0, t; }"
        : "=r"(a) : "l"(p));
    return a;
}
__device__ __forceinline__ void ldsm4(uint32_t* r, uint32_t addr) {
    asm volatile("ldmatrix.sync.aligned.m8n8.x4.shared.b16 {%0,%1,%2,%3}, [%4];"
        : "=r"(r[0]), "=r"(r[1]), "=r"(r[2]), "=r"(r[3]) : "r"(addr));
}
__device__ __forceinline__ void ldsm4t(uint32_t* r, uint32_t addr) {
    asm volatile("ldmatrix.sync.aligned.m8n8.x4.trans.shared.b16 {%0,%1,%2,%3}, [%4];"
        : "=r"(r[0]), "=r"(r[1]), "=r"(r[2]), "=r"(r[3]) : "r"(addr));
}
__device__ __forceinline__ void mma16816(float* c, const uint32_t* a,
                                         const uint32_t* b) {
    asm volatile(
        "mma.sync.aligned.m16n8k16.row.col.f32.bf16.bf16.f32 "
        "{%0,%1,%2,%3}, {%4,%5,%6,%7}, {%8,%9}, {%0,%1,%2,%3};"
        : "+f"(c[0]), "+f"(c[1]), "+f"(c[2]), "+f"(c[3])
        : "r"(a[0]), "r"(a[1]), "r"(a[2]), "r"(a[3]), "r"(b[0]), "r"(b[1]));
}
#define SW128(x) ((x) ^ (((x) >> 3) & 0x70))

// ---------------- TMA / mbarrier --------------------------------------------
#define MBAR_INIT(mb, c) asm volatile("mbarrier.init.shared.b64 [%0], %1;" :: "r"((uint32_t)(mb)), "r"((uint32_t)(c)) : "memory")
#define MBAR_EXPECT_TX(mb, tx) asm volatile("mbarrier.arrive.expect_tx.shared.b64 _, [%0], %1;" :: "r"((uint32_t)(mb)), "r"((uint32_t)(tx)) : "memory")
__device__ __forceinline__ void mbar_wait(uint32_t mb, uint32_t ph) {
    asm volatile(
        "{\n\t.reg .pred P1;\n\t"
        "WL_%=:\n\t"
        "mbarrier.try_wait.parity.acquire.cta.shared::cta.b64 P1, [%0], %1, 0x989680;\n\t"
        "@P1 bra.uni WD_%=;\n\t"
        "bra.uni WL_%=;\n\t"
        "WD_%=:\n\t}"
        :: "r"(mb), "r"(ph) : "memory");
}
__device__ __forceinline__ void tma2d(uint32_t dst, const void* map,
                                      int x, int y, uint32_t mbar) {
    asm volatile(
        "cp.async.bulk.tensor.2d.shared::cta.global.tile.mbarrier::complete_tx::bytes "
        "[%0], [%1, {%2, %3}], [%4];"
        :: "r"(dst), "l"(map), "r"(x), "r"(y), "r"(mbar) : "memory");
}

// ---------------- fused split fp32 -> bf16 hi/lo (grid-stride, MLP=2) -------
__global__ __launch_bounds__(256)
void split_all(const float* __restrict__ x,  const float* __restrict__ wq,
               const float* __restrict__ wk, const float* __restrict__ wv,
               const float* __restrict__ wo, int total4)
{
    const int XN4 = MTOT * DIMC / 4;     // 786432
    const int WN4 = PER / 4;             // 147456
    for (int i = blockIdx.x * blockDim.x + threadIdx.x; i < total4;
         i += gridDim.x * blockDim.x) {
        const float* src;
        __nv_bfloat16 *hi, *lo;
        int soff, doff;
        if (i < XN4) {
            src = x; hi = g_xh; lo = g_xl; soff = i; doff = i;
        } else {
            int j = i - XN4;
            int r = j / WN4;
            soff = j - r * WN4;
            if (r == 0)      { src = wq; hi = g_wh;  lo = g_wl;  doff = soff; }
            else if (r == 1) { src = wk; hi = g_wh;  lo = g_wl;  doff = soff + WN4; }
            else if (r == 2) { src = wv; hi = g_wh;  lo = g_wl;  doff = soff + 2 * WN4; }
            else             { src = wo; hi = g_woh; lo = g_wol; doff = soff; }
        }
        float4 v = reinterpret_cast<const float4*>(src)[soff];
        __nv_bfloat16 h0 = __float2bfloat16(v.x), h1 = __float2bfloat16(v.y);
        __nv_bfloat16 h2 = __float2bfloat16(v.z), h3 = __float2bfloat16(v.w);
        __nv_bfloat16 l0 = __float2bfloat16(v.x - __bfloat162float(h0));
        __nv_bfloat16 l1 = __float2bfloat16(v.y - __bfloat162float(h1));
        __nv_bfloat16 l2 = __float2bfloat16(v.z - __bfloat162float(h2));
        __nv_bfloat16 l3 = __float2bfloat16(v.w - __bfloat162float(h3));
        uint2 hp, lp;
        hp.x = (uint32_t)__bfloat16_as_ushort(h0) | ((uint32_t)__bfloat16_as_ushort(h1) << 16);
        hp.y = (uint32_t)__bfloat16_as_ushort(h2) | ((uint32_t)__bfloat16_as_ushort(h3) << 16);
        lp.x = (uint32_t)__bfloat16_as_ushort(l0) | ((uint32_t)__bfloat16_as_ushort(l1) << 16);
        lp.y = (uint32_t)__bfloat16_as_ushort(l2) | ((uint32_t)__bfloat16_as_ushort(l3) << 16);
        reinterpret_cast<uint2*>(hi)[doff] = hp;
        reinterpret_cast<uint2*>(lo)[doff] = lp;
    }
}

// ---------------- TMA-fed split-bf16 NT GEMM (validated champion) -----------
#define GST   49152
#define GSA_L 16384
#define GSB_H 32768
#define GSB_L 40960
#define GEMM_DSMEM (2 * GST + 1024)

__global__ __launch_bounds__(256)
void gemm_tma(const __grid_constant__ CUtensorMap mAh,
              const __grid_constant__ CUtensorMap mAl,
              const __grid_constant__ CUtensorMap mBh,
              const __grid_constant__ CUtensorMap mBl,
              float* __restrict__ C, const float* __restrict__ bias,
              int Ncols, size_t strideC)
{
    extern __shared__ char dsm[];
    __shared__ __align__(8) uint64_t mbarrier_s[2];
    const int tid = threadIdx.x;
    const int w = tid >> 5, lane = tid & 31;
    const int wr = w >> 1, wc = w & 1;
    const int m0 = blockIdx.y * 128, n0 = blockIdx.x * 64;
    const int z = blockIdx.z;
    const int yB = z * DIMC + n0;
    C += (size_t)z * strideC;

    const uint32_t sb = (smem_u32(dsm) + 1023u) & ~1023u;
    const uint32_t mb0 = smem_u32(&mbarrier_s[0]);
    const uint32_t mb1 = smem_u32(&mbarrier_s[1]);

    if (tid == 0) { MBAR_INIT(mb0, 1); MBAR_INIT(mb1, 1); }
    __syncthreads();

    if (tid == 0) {
#pragma unroll
        for (int s = 0; s < 2; ++s) {
            uint32_t mb = s ? mb1 : mb0;
            uint32_t base = sb + s * GST;
            MBAR_EXPECT_TX(mb, GST);
            tma2d(base,          &mAh, s * 64, m0, mb);
            tma2d(base + GSA_L,  &mAl, s * 64, m0, mb);
            tma2d(base + GSB_H,  &mBh, s * 64, yB, mb);
            tma2d(base + GSB_L,  &mBl, s * 64, yB, mb);
        }
    }

    float acc[2][4][4];
#pragma unroll
    for (int i = 0; i < 2; i++)
#pragma unroll
        for (int j = 0; j < 4; j++)
#pragma unroll
            for (int t = 0; t < 4; t++) acc[i][j][t] = 0.f;

    const int rA = lane & 15;
    const int cA = (lane >> 4) * 8;
    const int rB = ((lane >> 4) & 1) * 8 + (lane & 7);
    const int cB = ((lane >> 3) & 1) * 8;
    const int NCH = KDIM / 64;

    for (int c = 0; c < NCH; ++c) {
        const int b = c & 1;
        mbar_wait(b ? mb1 : mb0, (c >> 1) & 1);
        const uint32_t base = sb + b * GST;
#pragma unroll
        for (int ks = 0; ks < 4; ++ks) {
            uint32_t aH[2][4], aL[2][4], bH[4][2], bL[4][2];
#pragma unroll
            for (int mi = 0; mi < 2; ++mi) {
                uint32_t off = (uint32_t)((wr * 32 + mi * 16 + rA) * 128
                             + (ks * 16 + cA) * 2);
                uint32_t sw = SW128(off);
                ldsm4(aH[mi], base + sw);
                ldsm4(aL[mi], base + GSA_L + sw);
            }
#pragma unroll
            for (int njj = 0; njj < 2; ++njj) {
                uint32_t off = (uint32_t)((wc * 32 + njj * 16 + rB) * 128
                             + (ks * 16 + cB) * 2);
                uint32_t sw = SW128(off);
                uint32_t r[4];
                ldsm4(r, base + GSB_H + sw);
                bH[njj * 2][0] = r[0]; bH[njj * 2][1] = r[1];
                bH[njj * 2 + 1][0] = r[2]; bH[njj * 2 + 1][1] = r[3];
                ldsm4(r, base + GSB_L + sw);
                bL[njj * 2][0] = r[0]; bL[njj * 2][1] = r[1];
                bL[njj * 2 + 1][0] = r[2]; bL[njj * 2 + 1][1] = r[3];
            }
#pragma unroll
            for (int mi = 0; mi < 2; ++mi)
#pragma unroll
                for (int nj = 0; nj < 4; ++nj) {
                    mma16816(acc[mi][nj], aH[mi], bH[nj]);
                    mma16816(acc[mi][nj], aH[mi], bL[nj]);
                    mma16816(acc[mi][nj], aL[mi], bH[nj]);
                }
        }
        __syncthreads();
        if (c + 2 < NCH && tid == 0) {
            uint32_t mb = b ? mb1 : mb0;
            uint32_t base2 = sb + b * GST;
            MBAR_EXPECT_TX(mb, GST);
            tma2d(base2,         &mAh, (c + 2) * 64, m0, mb);
            tma2d(base2 + GSA_L, &mAl, (c + 2) * 64, m0, mb);
            tma2d(base2 + GSB_H, &mBh, (c + 2) * 64, yB, mb);
            tma2d(base2 + GSB_L, &mBl, (c + 2) * 64, yB, mb);
        }
    }

#pragma unroll
    for (int mi = 0; mi < 2; ++mi) {
        int gr = m0 + wr * 32 + mi * 16 + (lane >> 2);
#pragma unroll
        for (int nj = 0; nj < 4; ++nj) {
            int gc = n0 + wc * 32 + nj * 8 + (lane & 3) * 2;
            float2 v0, v1;
            v0.x = acc[mi][nj][0]; v0.y = acc[mi][nj][1];
            v1.x = acc[mi][nj][2]; v1.y = acc[mi][nj][3];
            if (bias) {
                float b0 = bias[gc], b1 = bias[gc + 1];
                v0.x += b0; v0.y += b1; v1.x += b0; v1.y += b1;
            }
            *reinterpret_cast<float2*>(C + (size_t)gr * Ncols + gc) = v0;
            *reinterpret_cast<float2*>(C + (size_t)(gr + 8) * Ncols + gc) = v1;
        }
    }
}

// ---------------- SPD log-projection (merged Q+K) ----------------------------
__global__ __launch_bounds__(256)
void lproj_qk(const float* __restrict__ qkv,
              const float* __restrict__ sq_w, const float* __restrict__ sq_b,
              const float* __restrict__ sk_w, const float* __restrict__ sk_b,
              __nv_bfloat16* __restrict__ lqp, __nv_bfloat16* __restrict__ lkp,
              float* __restrict__ lq2, float* __restrict__ lk2)
{
    __shared__ float s_w[RK][HD];
    __shared__ float s_b[RK];
    __shared__ float s_q[128][HD + 1];

    const int sel  = blockIdx.y;
    const float* src  = qkv + (size_t)sel * MTOT * DIMC;
    const float* w    = sel ? sk_w : sq_w;
    const float* bias = sel ? sk_b : sq_b;
    __nv_bfloat16* lp = sel ? lkp : lqp;
    float* l2arr      = sel ? lk2 : lq2;

    const int bid  = blockIdx.x;
    const int bh   = bid >> 3;
    const int tile = bid & 7;
    const int b    = bh / NH;
    const int h    = bh - b * NH;
    const int tid  = threadIdx.x;

    ((float*)s_w)[tid]       = w[tid & 511];
    ((float*)s_w)[tid + 256] = w[(tid + 256) & 511];
    if (tid < RK) s_b[tid] = bias[tid];

    const float* base = src + ((size_t)(b * SEQ) + tile * 128) * DIMC + h * HD;
#pragma unroll
    for (int u = 0; u < 8; ++u) {
        int s   = tid + u * 256;
        int row = s >> 4;
        int c4  = (s & 15) << 2;
        float4 v = *reinterpret_cast<const float4*>(base + (size_t)row * DIMC + c4);
        s_q[row][c4 + 0] = v.x; s_q[row][c4 + 1] = v.y;
        s_q[row][c4 + 2] = v.z; s_q[row][c4 + 3] = v.w;
    }
    __syncthreads();

    const int token = tid >> 1;
    const int r0    = (tid & 1) * 4;
    float z0 = s_b[r0 + 0], z1 = s_b[r0 + 1], z2 = s_b[r0 + 2], z3 = s_b[r0 + 3];
#pragma unroll
    for (int d = 0; d < HD; ++d) {
        float q = s_q[token][d];
        z0 = fmaf(q, s_w[r0 + 0][d], z0);
        z1 = fmaf(q, s_w[r0 + 1][d], z1);
        z2 = fmaf(q, s_w[r0 + 2][d], z2);
        z3 = fmaf(q, s_w[r0 + 3][d], z3);
    }
    float zz[4] = {z0, z1, z2, z3};
    float hi4[4], lo4[4];
    float s2 = 0.f;
#pragma unroll
    for (int i = 0; i < 4; ++i) {
        float z = zz[i];
        float sp = (z > 20.f) ? z : log1pf(expf(z));
        float l = 0.125f * logf(sp + 1e-6f + 1e-8f);
        s2 = fmaf(l, l, s2);
        float h = __bfloat162float(__float2bfloat16(l));
        hi4[i] = h;
        lo4[i] = l - h;
    }
    s2 += __shfl_xor_sync(0xffffffffu, s2, 1);

    const size_t t = (size_t)bh * SEQ + tile * 128 + token;
    uint2 hp, lq;
    hp.x = pack_bf16x2(hi4[0], hi4[1]);
    hp.y = pack_bf16x2(hi4[2], hi4[3]);
    lq.x = pack_bf16x2(lo4[0], lo4[1]);
    lq.y = pack_bf16x2(lo4[2], lo4[3]);
    *reinterpret_cast<uint2*>(lp + t * 16 + r0)     = hp;
    *reinterpret_cast<uint2*>(lp + t * 16 + 8 + r0) = lq;
    if ((tid & 1) == 0) l2arr[t] = s2;
}

// ---------------- SV precompute ---------------------------------------------
__global__ __launch_bounds__(256)
void svsum_kernel()
{
    __shared__ float part[4][HD];
    const int bh = blockIdx.x;
    const int b = bh / NH, h = bh - b * NH;
    const int tid = threadIdx.x;
    const int d = tid & 63, seg = tid >> 6;
    const float* Vp = g_qkv + (size_t)2 * MTOT * DIMC
                    + (size_t)(b * SEQ) * DIMC + h * HD + d;
    float s = 0.f;
    for (int k = seg * 256; k < seg * 256 + 256; ++k)
        s += Vp[(size_t)k * DIMC];
    part[seg][d] = s;
    __syncthreads();
    if (tid < HD)
        g_sv[bh * HD + tid] = part[0][tid] + part[1][tid]
                            + part[2][tid] + part[3][tid];
}

// ---------------- geodesic attention (validated R9/R10) ----------------------
#define AKT 64
#define UP  72
#define LQP 24

__global__ __launch_bounds__(256, 2)
void attn_mma()
{
    __shared__ __align__(16) __nv_bfloat16 s_lq [128][LQP];
    __shared__ __align__(16) __nv_bfloat16 s_lkA[AKT][LQP];
    __shared__ __align__(16) __nv_bfloat16 s_lkB[AKT][LQP];
    __shared__ float s_lk2[AKT];
    __shared__ float s_sv[HD];
    __shared__ float s_linv[128];
    __shared__ __align__(16) __nv_bfloat16 s_v[AKT][UP];

    const int qb = blockIdx.x, bh = blockIdx.y;
    const int b = bh / NH, h = bh - b * NH;
    const int tid = threadIdx.x, lane = tid & 31, w = tid >> 5;
    const int qq = lane >> 2, ii = lane & 3;
    const int rowq = 16 * w + qq;

    {
        int row = tid >> 1, half = tid & 1;
        *reinterpret_cast<uint4*>(&s_lq[row][half * 8]) =
            *reinterpret_cast<const uint4*>(
                g_lqp + ((size_t)bh * SEQ + qb * 128 + row) * 16 + half * 8);
    }
    if (tid < HD) s_sv[tid] = g_sv[bh * HD + tid];
    const float lq2_0 = g_lq2[(size_t)bh * SEQ + qb * 128 + rowq];
    const float lq2_1 = g_lq2[(size_t)bh * SEQ + qb * 128 + rowq + 8];
    __syncthreads();

    uint32_t aF[4];
    ldsm4(aF, smem_u32(&s_lq[16 * w + (lane & 15)][(lane >> 4) * 8]));

    const float* Vp  = g_qkv + (size_t)2 * MTOT * DIMC
                     + (size_t)(b * SEQ) * DIMC + h * HD;
    const __nv_bfloat16* Lkp = g_lkp + (size_t)bh * SEQ * 16;
    const float* Lk2 = g_lk2 + (size_t)bh * SEQ;

    float acc[8][4];
#pragma unroll
    for (int i = 0; i < 8; i++)
#pragma unroll
        for (int j = 0; j < 4; j++) acc[i][j] = 0.f;
    float us0 = 0.f, us1 = 0.f;

    const int rB = ((lane >> 4) & 1) * 8 + (lane & 7);
    const int cB = ((lane >> 3) & 1) * 8;
    const int rL = lane & 15, cL = (lane >> 4) * 8;

    for (int kt = 0; kt < SEQ / AKT; ++kt) {
        const int key0 = kt * AKT;
        __syncthreads();
        if (tid < 64) {
            uint4 hv = *reinterpret_cast<const uint4*>(Lkp + (key0 + tid) * 16);
            *reinterpret_cast<uint4*>(&s_lkA[tid][0]) = hv;
            *reinterpret_cast<uint4*>(&s_lkA[tid][8]) = hv;
        } else if (tid < 128) {
            int r = tid - 64;
            uint4 lv = *reinterpret_cast<const uint4*>(Lkp + (key0 + r) * 16 + 8);
            *reinterpret_cast<uint4*>(&s_lkB[r][0]) = lv;
            *reinterpret_cast<uint4*>(&s_lkB[r][8]) = make_uint4(0, 0, 0, 0);
        } else if (tid < 192) {
            s_lk2[tid - 128] = Lk2[key0 + tid - 128];
        }
#pragma unroll
        for (int u2 = 0; u2 < 4; ++u2) {
            int s = tid + u2 * 256;
            int key = s >> 4, d4 = (s & 15) * 4;
            float4 v = *(const float4*)(Vp + (size_t)(key0 + key) * DIMC + d4);
            uint2 pk;
            pk.x = pack_bf16x2(v.x, v.y);
            pk.y = pack_bf16x2(v.z, v.w);
            *reinterpret_cast<uint2*>(&s_v[key][d4]) = pk;
        }
        __syncthreads();

        uint32_t uA[4][4];
#pragma unroll
        for (int hhalf = 0; hhalf < 2; ++hhalf) {
            float sacc[4][4];
#pragma unroll
            for (int i = 0; i < 4; i++)
#pragma unroll
                for (int j = 0; j < 4; j++) sacc[i][j] = 0.f;
#pragma unroll
            for (int nj = 0; nj < 2; ++nj) {
                int njj = 2 * hhalf + nj;
                uint32_t addr = (njj * 16 + rB) * (LQP * 2) + cB * 2;
                uint32_t r[4];
                ldsm4(r, smem_u32(s_lkA) + addr);
                uint32_t bb0[2] = {r[0], r[1]};
                uint32_t bb1[2] = {r[2], r[3]};
                uint32_t r2[4];
                ldsm4(r2, smem_u32(s_lkB) + addr);
                uint32_t bc0[2] = {r2[0], r2[1]};
                uint32_t bc1[2] = {r2[2], r2[3]};
                mma16816(sacc[2 * nj],     aF, bb0);
                mma16816(sacc[2 * nj],     aF, bc0);
                mma16816(sacc[2 * nj + 1], aF, bb1);
                mma16816(sacc[2 * nj + 1], aF, bc1);
            }
#pragma unroll
            for (int k = 0; k < 4; ++k) {
                int nc = 4 * hhalf + k;
                int col = 8 * nc + 2 * ii;
                float lk0 = s_lk2[col], lk1 = s_lk2[col + 1];
                float d00 = fmaf(-2.f, sacc[k][0], lq2_0 + lk0);
                float d01 = fmaf(-2.f, sacc[k][1], lq2_0 + lk1);
                float d10 = fmaf(-2.f, sacc[k][2], lq2_1 + lk0);
                float d11 = fmaf(-2.f, sacc[k][3], lq2_1 + lk1);
                d00 = fmaxf(d00, 1.5625e-14f);
                d01 = fmaxf(d01, 1.5625e-14f);
                d10 = fmaxf(d10, 1.5625e-14f);
                d11 = fmaxf(d11, 1.5625e-14f);
                float t00 = sqa(d00), t01 = sqa(d01);
                float t10 = sqa(d10), t11 = sqa(d11);
                const float c2 = -0.5f, c3 = 0.16666667f, c4 = -0.041666667f;
                float u00 = t00 * fmaf(t00, fmaf(t00, fmaf(t00, c4, c3), c2), 1.f);
                float u01 = t01 * fmaf(t01, fmaf(t01, fmaf(t01, c4, c3), c2), 1.f);
                float u10 = t10 * fmaf(t10, fmaf(t10, fmaf(t10, c4, c3), c2), 1.f);
                float u11 = t11 * fmaf(t11, fmaf(t11, fmaf(t11, c4, c3), c2), 1.f);
                us0 += u00 + u01;
                us1 += u10 + u11;
                int kc = nc >> 1;
                if ((nc & 1) == 0) {
                    uA[kc][0] = pack_bf16x2(u00, u01);
                    uA[kc][1] = pack_bf16x2(u10, u11);
                } else {
                    uA[kc][2] = pack_bf16x2(u00, u01);
                    uA[kc][3] = pack_bf16x2(u10, u11);
                }
            }
        }

#pragma unroll
        for (int kc = 0; kc < 4; ++kc) {
#pragma unroll
            for (int vc = 0; vc < 4; ++vc) {
                uint32_t r[4];
                ldsm4t(r, smem_u32(&s_v[16 * kc + rL][16 * vc + cL]));
                mma16816(acc[2 * vc],     uA[kc], r);
                mma16816(acc[2 * vc + 1], uA[kc], r + 2);
            }
        }
    }

    us0 += __shfl_xor_sync(0xffffffffu, us0, 1);
    us0 += __shfl_xor_sync(0xffffffffu, us0, 2);
    us1 += __shfl_xor_sync(0xffffffffu, us1, 1);
    us1 += __shfl_xor_sync(0xffffffffu, us1, 2);
    if (ii == 0) {
        s_linv[rowq]     = 1.f / (1024.f - us0);
        s_linv[rowq + 8] = 1.f / (1024.f - us1);
    }
    __syncthreads();

    const float ilo = s_linv[rowq], ihi = s_linv[rowq + 8];
    const size_t rowb = (size_t)(b * SEQ + qb * 128) * DIMC + h * HD;
#pragma unroll
    for (int nc = 0; nc < 8; ++nc) {
        int c = 8 * nc + ii * 2;
        float sv0 = s_sv[c], sv1 = s_sv[c + 1];
        float o00 = (sv0 - acc[nc][0]) * ilo;
        float o01 = (sv1 - acc[nc][1]) * ilo;
        float o10 = (sv0 - acc[nc][2]) * ihi;
        float o11 = (sv1 - acc[nc][3]) * ihi;
        float h00 = __bfloat162float(__float2bfloat16(o00));
        float h01 = __bfloat162float(__float2bfloat16(o01));
        float h10 = __bfloat162float(__float2bfloat16(o10));
        float h11 = __bfloat162float(__float2bfloat16(o11));
        size_t a0 = rowb + (size_t)rowq * DIMC + c;
        size_t a1 = rowb + (size_t)(rowq + 8) * DIMC + c;
        *reinterpret_cast<uint32_t*>(g_ch + a0) = pack_bf16x2(h00, h01);
        *reinterpret_cast<uint32_t*>(g_cl + a0) = pack_bf16x2(o00 - h00, o01 - h01);
        *reinterpret_cast<uint32_t*>(g_ch + a1) = pack_bf16x2(h10, h11);
        *reinterpret_cast<uint32_t*>(g_cl + a1) = pack_bf16x2(o10 - h10, o11 - h11);
    }
}

// ---------------- KL term (validated R13: 256-block power-of-two tree) ------
__global__ __launch_bounds__(256)
void kl_partial(const float* __restrict__ m0, const float* __restrict__ l0,
                const float* __restrict__ m1, const float* __restrict__ l1,
                const float* __restrict__ m2, const float* __restrict__ l2,
                const float* __restrict__ m3, const float* __restrict__ l3)
{
    const int PER4 = PER / 4;
    const int TOT4 = 4 * PER4;
    const float L2E2 = 2.0f * 1.4426950408889634f;
    float s = 0.f;
    for (int i4 = blockIdx.x * blockDim.x + threadIdx.x; i4 < TOT4;
         i4 += gridDim.x * blockDim.x) {
        int p   = i4 / PER4;
        int off = i4 - p * PER4;
        const float* mp = (p == 0) ? m0 : (p == 1) ? m1 : (p == 2) ? m2 : m3;
        const float* lp = (p == 0) ? l0 : (p == 1) ? l1 : (p == 2) ? l2 : l3;
        float4 mu = reinterpret_cast<const float4*>(mp)[off];
        float4 ls = reinterpret_cast<const float4*>(lp)[off];
        s += 0.5f * (ex2a(L2E2 * ls.x) + mu.x * mu.x - 1.f - 2.f * ls.x);
        s += 0.5f * (ex2a(L2E2 * ls.y) + mu.y * mu.y - 1.f - 2.f * ls.y);
        s += 0.5f * (ex2a(L2E2 * ls.z) + mu.z * mu.z - 1.f - 2.f * ls.z);
        s += 0.5f * (ex2a(L2E2 * ls.w) + mu.w * mu.w - 1.f - 2.f * ls.w);
    }
    __shared__ float red[256];
    red[threadIdx.x] = s;
    __syncthreads();
    for (int w = 128; w > 0; w >>= 1) {
        if (threadIdx.x < w) red[threadIdx.x] += red[threadIdx.x + w];
        __syncthreads();
    }
    if (threadIdx.x == 0) g_klpart[blockIdx.x] = red[0];
}

__global__ void kl_final(float* __restrict__ dst)
{
    __shared__ float red[256];
    red[threadIdx.x] = g_klpart[threadIdx.x];
    __syncthreads();
    for (int w = 128; w > 0; w >>= 1) {
        if (threadIdx.x < w) red[threadIdx.x] += red[threadIdx.x + w];
        __syncthreads();
    }
    if (threadIdx.x == 0) *dst = red[0];
}

// ---------------- host: tensor map encoding ---------------------------------
typedef CUresult (*PFN_tmEnc)(CUtensorMap*, CUtensorMapDataType, cuuint32_t,
                              void*, const cuuint64_t*, const cuuint64_t*,
                              const cuuint32_t*, const cuuint32_t*,
                              CUtensorMapInterleave, CUtensorMapSwizzle,
                              CUtensorMapL2promotion, CUtensorMapFloatOOBfill);

static void encode_map(PFN_tmEnc fn, CUtensorMap* m, void* ptr,
                       unsigned long long rows, unsigned boxRows)
{
    cuuint64_t dims[2]    = {(cuuint64_t)KDIM, (cuuint64_t)rows};
    cuuint64_t strides[1] = {(cuuint64_t)KDIM * 2};
    cuuint32_t box[2]     = {64u, boxRows};
    cuuint32_t es[2]      = {1u, 1u};
    fn(m, CU_TENSOR_MAP_DATA_TYPE_BFLOAT16, 2, ptr, dims, strides, box, es,
       CU_TENSOR_MAP_INTERLEAVE_NONE, CU_TENSOR_MAP_SWIZZLE_128B,
       CU_TENSOR_MAP_L2_PROMOTION_L2_128B, CU_TENSOR_MAP_FLOAT_OOB_FILL_NONE);
}

// ---------------- launcher (exact R10/R13 champion graph) --------------------
extern "C" void kernel_launch(void* const* d_in, const int* in_sizes, int n_in,
                              void* d_out, int out_size)
{
    const float* x     = (const float*)d_in[0];
    const float* wq_mu = (const float*)d_in[1];
    const float* wq_ls = (const float*)d_in[2];
    const float* wk_mu = (const float*)d_in[3];
    const float* wk_ls = (const float*)d_in[4];
    const float* wv_mu = (const float*)d_in[5];
    const float* wv_ls = (const float*)d_in[6];
    const float* wo_mu = (const float*)d_in[7];
    const float* wo_ls = (const float*)d_in[8];
    const float* wo_b  = (const float*)d_in[9];
    const float* sq_w  = (const float*)d_in[10];
    const float* sq_b  = (const float*)d_in[11];
    const float* sk_w  = (const float*)d_in[12];
    const float* sk_b  = (const float*)d_in[13];
    float* out = (float*)d_out;

    float *qkv_d, *lq2_d, *lk2_d;
    __nv_bfloat16 *lqp_d, *lkp_d;
    __nv_bfloat16 *xh_d, *xl_d, *wh_d, *wl_d, *woh_d, *wol_d, *ch_d, *cl_d;
    cudaGetSymbolAddress((void**)&qkv_d, g_qkv);
    cudaGetSymbolAddress((void**)&lqp_d, g_lqp);
    cudaGetSymbolAddress((void**)&lkp_d, g_lkp);
    cudaGetSymbolAddress((void**)&lq2_d, g_lq2);
    cudaGetSymbolAddress((void**)&lk2_d, g_lk2);
    cudaGetSymbolAddress((void**)&xh_d,  g_xh);
    cudaGetSymbolAddress((void**)&xl_d,  g_xl);
    cudaGetSymbolAddress((void**)&wh_d,  g_wh);
    cudaGetSymbolAddress((void**)&wl_d,  g_wl);
    cudaGetSymbolAddress((void**)&woh_d, g_woh);
    cudaGetSymbolAddress((void**)&wol_d, g_wol);
    cudaGetSymbolAddress((void**)&ch_d,  g_ch);
    cudaGetSymbolAddress((void**)&cl_d,  g_cl);

    static PFN_tmEnc tmEnc = nullptr;
    static cudaStream_t s2 = nullptr;
    static cudaEvent_t evRoot = nullptr, evQKV = nullptr, evSide = nullptr;
    if (!tmEnc) {
        cudaDriverEntryPointQueryResult qr;
        cudaGetDriverEntryPoint("cuTensorMapEncodeTiled", (void**)&tmEnc,
                                cudaEnableDefault, &qr);
        cudaStreamCreateWithFlags(&s2, cudaStreamNonBlocking);
        cudaEventCreateWithFlags(&evRoot, cudaEventDisableTiming);
        cudaEventCreateWithFlags(&evQKV,  cudaEventDisableTiming);
        cudaEventCreateWithFlags(&evSide, cudaEventDisableTiming);
    }
    CUtensorMap mXh, mXl, mWh, mWl, mCh, mCl, mOh, mOl;
    encode_map(tmEnc, &mXh, xh_d,  MTOT,     128);
    encode_map(tmEnc, &mXl, xl_d,  MTOT,     128);
    encode_map(tmEnc, &mWh, wh_d,  3 * DIMC, 64);
    encode_map(tmEnc, &mWl, wl_d,  3 * DIMC, 64);
    encode_map(tmEnc, &mCh, ch_d,  MTOT,     128);
    encode_map(tmEnc, &mCl, cl_d,  MTOT,     128);
    encode_map(tmEnc, &mOh, woh_d, DIMC,     64);
    encode_map(tmEnc, &mOl, wol_d, DIMC,     64);

    cudaFuncSetAttribute(gemm_tma, cudaFuncAttributeMaxDynamicSharedMemorySize,
                         GEMM_DSMEM);

    // fork side stream: KL reduction depends only on inputs
    cudaEventRecord(evRoot, 0);
    cudaStreamWaitEvent(s2, evRoot, 0);
    kl_partial<<<256, 256, 0, s2>>>(wq_mu, wq_ls, wk_mu, wk_ls,
                                    wv_mu, wv_ls, wo_mu, wo_ls);
    if (out_size > MTOT * DIMC) {
        kl_final<<<1, 256, 0, s2>>>(out + (size_t)out_size - 1);
    }

    const int TOTAL4 = MTOT * DIMC / 4 + 4 * (PER / 4);
    split_all<<<TOTAL4 / 512, 256>>>(x, wq_mu, wk_mu, wv_mu, wo_mu, TOTAL4);

    gemm_tma<<<dim3(DIMC / 64, MTOT / 128, 3), 256, GEMM_DSMEM>>>(
        mXh, mXl, mWh, mWl, qkv_d, nullptr, DIMC, (size_t)MTOT * DIMC);
    cudaEventRecord(evQKV, 0);

    // svsum on side stream (depends on V plane of QKV gemm)
    cudaStreamWaitEvent(s2, evQKV, 0);
    svsum_kernel<<<BH, 256, 0, s2>>>();
    cudaEventRecord(evSide, s2);

    // merged Q+K log-projection on main stream
    lproj_qk<<<dim3(BH * 8, 2), 256>>>(qkv_d, sq_w, sq_b, sk_w, sk_b,
                                       lqp_d, lkp_d, lq2_d, lk2_d);

    // join side stream before attention (needs g_sv; also joins KL)
    cudaStreamWaitEvent(0, evSide, 0);

    attn_mma<<<dim3(SEQ / 128, BH), 256>>>();

    gemm_tma<<<dim3(DIMC / 64, MTOT / 128, 1), 256, GEMM_DSMEM>>>(
        mCh, mCl, mOh, mOl, out, wo_b, DIMC, 0);
}

// round 17
// speedup vs baseline: 1.4966x; 1.4966x over previous
// R16: byte-equivalent resubmission of the R10/R13 champion (223.3 us) to
// disambiguate clock-state noise from code regression. No functional changes.
#include <cuda_runtime.h>
#include <cuda.h>
#include <cuda_bf16.h>
#include <cstdint>
#include <math.h>

#define BATCH 4
#define SEQ   1024
#define DIMC  768
#define NH    12
#define HD    64
#define RK    8
#define MTOT  (BATCH*SEQ)     /* 4096 */
#define BH    (BATCH*NH)      /* 48   */
#define KDIM  768
#define PER   (DIMC*DIMC)

// ---------------- scratch (device globals; no allocation allowed) ----------
__device__ __align__(16) float g_qkv[3*MTOT*DIMC];     // q,k,v planes
__device__ __align__(16) __nv_bfloat16 g_lqp[BH*SEQ*16]; // [hi8|lo8] scaled
__device__ __align__(16) __nv_bfloat16 g_lkp[BH*SEQ*16];
__device__ __align__(16) float g_lq2[BH*SEQ];
__device__ __align__(16) float g_lk2[BH*SEQ];
__device__ __align__(16) float g_sv [BH*HD];
__device__ float g_klpart[256];
__device__ __align__(1024) __nv_bfloat16 g_xh [MTOT*DIMC];
__device__ __align__(1024) __nv_bfloat16 g_xl [MTOT*DIMC];
__device__ __align__(1024) __nv_bfloat16 g_wh [3*PER];
__device__ __align__(1024) __nv_bfloat16 g_wl [3*PER];
__device__ __align__(1024) __nv_bfloat16 g_woh[PER];
__device__ __align__(1024) __nv_bfloat16 g_wol[PER];
__device__ __align__(1024) __nv_bfloat16 g_ch [MTOT*DIMC];
__device__ __align__(1024) __nv_bfloat16 g_cl [MTOT*DIMC];

// ---------------- fast approx helpers --------------------------------------
__device__ __forceinline__ float ex2a(float x) {
    float y; asm("ex2.approx.f32 %0, %1;" : "=f"(y) : "f"(x)); return y;
}
__device__ __forceinline__ float sqa(float x) {
    float y; asm("sqrt.approx.f32 %0, %1;" : "=f"(y) : "f"(x)); return y;
}
__device__ __forceinline__ uint32_t pack_bf16x2(float lo, float hi) {
    uint32_t r;
    asm("cvt.rn.bf16x2.f32 %0, %1, %2;" : "=r"(r) : "f"(hi), "f"(lo));
    return r;
}

// ---------------- smem / mma primitives -------------------------------------
__device__ __forceinline__ uint32_t smem_u32(const void* p) {
    uint32_t a;
    asm("{ .reg .u64 t; cvta.to.shared.u64 t, %1; cvt.u32.u64 %0, t; }"
        : "=r"(a) : "l"(p));
    return a;
}
__device__ __forceinline__ void ldsm4(uint32_t* r, uint32_t addr) {
    asm volatile("ldmatrix.sync.aligned.m8n8.x4.shared.b16 {%0,%1,%2,%3}, [%4];"
        : "=r"(r[0]), "=r"(r[1]), "=r"(r[2]), "=r"(r[3]) : "r"(addr));
}
__device__ __forceinline__ void ldsm4t(uint32_t* r, uint32_t addr) {
    asm volatile("ldmatrix.sync.aligned.m8n8.x4.trans.shared.b16 {%0,%1,%2,%3}, [%4];"
        : "=r"(r[0]), "=r"(r[1]), "=r"(r[2]), "=r"(r[3]) : "r"(addr));
}
__device__ __forceinline__ void mma16816(float* c, const uint32_t* a,
                                         const uint32_t* b) {
    asm volatile(
        "mma.sync.aligned.m16n8k16.row.col.f32.bf16.bf16.f32 "
        "{%0,%1,%2,%3}, {%4,%5,%6,%7}, {%8,%9}, {%0,%1,%2,%3};"
        : "+f"(c[0]), "+f"(c[1]), "+f"(c[2]), "+f"(c[3])
        : "r"(a[0]), "r"(a[1]), "r"(a[2]), "r"(a[3]), "r"(b[0]), "r"(b[1]));
}
#define SW128(x) ((x) ^ (((x) >> 3) & 0x70))

// ---------------- TMA / mbarrier --------------------------------------------
#define MBAR_INIT(mb, c) asm volatile("mbarrier.init.shared.b64 [%0], %1;" :: "r"((uint32_t)(mb)), "r"((uint32_t)(c)) : "memory")
#define MBAR_EXPECT_TX(mb, tx) asm volatile("mbarrier.arrive.expect_tx.shared.b64 _, [%0], %1;" :: "r"((uint32_t)(mb)), "r"((uint32_t)(tx)) : "memory")
__device__ __forceinline__ void mbar_wait(uint32_t mb, uint32_t ph) {
    asm volatile(
        "{\n\t.reg .pred P1;\n\t"
        "WL_%=:\n\t"
        "mbarrier.try_wait.parity.acquire.cta.shared::cta.b64 P1, [%0], %1, 0x989680;\n\t"
        "@P1 bra.uni WD_%=;\n\t"
        "bra.uni WL_%=;\n\t"
        "WD_%=:\n\t}"
        :: "r"(mb), "r"(ph) : "memory");
}
__device__ __forceinline__ void tma2d(uint32_t dst, const void* map,
                                      int x, int y, uint32_t mbar) {
    asm volatile(
        "cp.async.bulk.tensor.2d.shared::cta.global.tile.mbarrier::complete_tx::bytes "
        "[%0], [%1, {%2, %3}], [%4];"
        :: "r"(dst), "l"(map), "r"(x), "r"(y), "r"(mbar) : "memory");
}

// ---------------- fused split fp32 -> bf16 hi/lo (grid-stride, MLP=2) -------
__global__ __launch_bounds__(256)
void split_all(const float* __restrict__ x,  const float* __restrict__ wq,
               const float* __restrict__ wk, const float* __restrict__ wv,
               const float* __restrict__ wo, int total4)
{
    const int XN4 = MTOT * DIMC / 4;     // 786432
    const int WN4 = PER / 4;             // 147456
    for (int i = blockIdx.x * blockDim.x + threadIdx.x; i < total4;
         i += gridDim.x * blockDim.x) {
        const float* src;
        __nv_bfloat16 *hi, *lo;
        int soff, doff;
        if (i < XN4) {
            src = x; hi = g_xh; lo = g_xl; soff = i; doff = i;
        } else {
            int j = i - XN4;
            int r = j / WN4;
            soff = j - r * WN4;
            if (r == 0)      { src = wq; hi = g_wh;  lo = g_wl;  doff = soff; }
            else if (r == 1) { src = wk; hi = g_wh;  lo = g_wl;  doff = soff + WN4; }
            else if (r == 2) { src = wv; hi = g_wh;  lo = g_wl;  doff = soff + 2 * WN4; }
            else             { src = wo; hi = g_woh; lo = g_wol; doff = soff; }
        }
        float4 v = reinterpret_cast<const float4*>(src)[soff];
        __nv_bfloat16 h0 = __float2bfloat16(v.x), h1 = __float2bfloat16(v.y);
        __nv_bfloat16 h2 = __float2bfloat16(v.z), h3 = __float2bfloat16(v.w);
        __nv_bfloat16 l0 = __float2bfloat16(v.x - __bfloat162float(h0));
        __nv_bfloat16 l1 = __float2bfloat16(v.y - __bfloat162float(h1));
        __nv_bfloat16 l2 = __float2bfloat16(v.z - __bfloat162float(h2));
        __nv_bfloat16 l3 = __float2bfloat16(v.w - __bfloat162float(h3));
        uint2 hp, lp;
        hp.x = (uint32_t)__bfloat16_as_ushort(h0) | ((uint32_t)__bfloat16_as_ushort(h1) << 16);
        hp.y = (uint32_t)__bfloat16_as_ushort(h2) | ((uint32_t)__bfloat16_as_ushort(h3) << 16);
        lp.x = (uint32_t)__bfloat16_as_ushort(l0) | ((uint32_t)__bfloat16_as_ushort(l1) << 16);
        lp.y = (uint32_t)__bfloat16_as_ushort(l2) | ((uint32_t)__bfloat16_as_ushort(l3) << 16);
        reinterpret_cast<uint2*>(hi)[doff] = hp;
        reinterpret_cast<uint2*>(lo)[doff] = lp;
    }
}

// ---------------- TMA-fed split-bf16 NT GEMM (validated champion) -----------
#define GST   49152
#define GSA_L 16384
#define GSB_H 32768
#define GSB_L 40960
#define GEMM_DSMEM (2 * GST + 1024)

__global__ __launch_bounds__(256)
void gemm_tma(const __grid_constant__ CUtensorMap mAh,
              const __grid_constant__ CUtensorMap mAl,
              const __grid_constant__ CUtensorMap mBh,
              const __grid_constant__ CUtensorMap mBl,
              float* __restrict__ C, const float* __restrict__ bias,
              int Ncols, size_t strideC)
{
    extern __shared__ char dsm[];
    __shared__ __align__(8) uint64_t mbarrier_s[2];
    const int tid = threadIdx.x;
    const int w = tid >> 5, lane = tid & 31;
    const int wr = w >> 1, wc = w & 1;
    const int m0 = blockIdx.y * 128, n0 = blockIdx.x * 64;
    const int z = blockIdx.z;
    const int yB = z * DIMC + n0;
    C += (size_t)z * strideC;

    const uint32_t sb = (smem_u32(dsm) + 1023u) & ~1023u;
    const uint32_t mb0 = smem_u32(&mbarrier_s[0]);
    const uint32_t mb1 = smem_u32(&mbarrier_s[1]);

    if (tid == 0) { MBAR_INIT(mb0, 1); MBAR_INIT(mb1, 1); }
    __syncthreads();

    if (tid == 0) {
#pragma unroll
        for (int s = 0; s < 2; ++s) {
            uint32_t mb = s ? mb1 : mb0;
            uint32_t base = sb + s * GST;
            MBAR_EXPECT_TX(mb, GST);
            tma2d(base,          &mAh, s * 64, m0, mb);
            tma2d(base + GSA_L,  &mAl, s * 64, m0, mb);
            tma2d(base + GSB_H,  &mBh, s * 64, yB, mb);
            tma2d(base + GSB_L,  &mBl, s * 64, yB, mb);
        }
    }

    float acc[2][4][4];
#pragma unroll
    for (int i = 0; i < 2; i++)
#pragma unroll
        for (int j = 0; j < 4; j++)
#pragma unroll
            for (int t = 0; t < 4; t++) acc[i][j][t] = 0.f;

    const int rA = lane & 15;
    const int cA = (lane >> 4) * 8;
    const int rB = ((lane >> 4) & 1) * 8 + (lane & 7);
    const int cB = ((lane >> 3) & 1) * 8;
    const int NCH = KDIM / 64;

    for (int c = 0; c < NCH; ++c) {
        const int b = c & 1;
        mbar_wait(b ? mb1 : mb0, (c >> 1) & 1);
        const uint32_t base = sb + b * GST;
#pragma unroll
        for (int ks = 0; ks < 4; ++ks) {
            uint32_t aH[2][4], aL[2][4], bH[4][2], bL[4][2];
#pragma unroll
            for (int mi = 0; mi < 2; ++mi) {
                uint32_t off = (uint32_t)((wr * 32 + mi * 16 + rA) * 128
                             + (ks * 16 + cA) * 2);
                uint32_t sw = SW128(off);
                ldsm4(aH[mi], base + sw);
                ldsm4(aL[mi], base + GSA_L + sw);
            }
#pragma unroll
            for (int njj = 0; njj < 2; ++njj) {
                uint32_t off = (uint32_t)((wc * 32 + njj * 16 + rB) * 128
                             + (ks * 16 + cB) * 2);
                uint32_t sw = SW128(off);
                uint32_t r[4];
                ldsm4(r, base + GSB_H + sw);
                bH[njj * 2][0] = r[0]; bH[njj * 2][1] = r[1];
                bH[njj * 2 + 1][0] = r[2]; bH[njj * 2 + 1][1] = r[3];
                ldsm4(r, base + GSB_L + sw);
                bL[njj * 2][0] = r[0]; bL[njj * 2][1] = r[1];
                bL[njj * 2 + 1][0] = r[2]; bL[njj * 2 + 1][1] = r[3];
            }
#pragma unroll
            for (int mi = 0; mi < 2; ++mi)
#pragma unroll
                for (int nj = 0; nj < 4; ++nj) {
                    mma16816(acc[mi][nj], aH[mi], bH[nj]);
                    mma16816(acc[mi][nj], aH[mi], bL[nj]);
                    mma16816(acc[mi][nj], aL[mi], bH[nj]);
                }
        }
        __syncthreads();
        if (c + 2 < NCH && tid == 0) {
            uint32_t mb = b ? mb1 : mb0;
            uint32_t base2 = sb + b * GST;
            MBAR_EXPECT_TX(mb, GST);
            tma2d(base2,         &mAh, (c + 2) * 64, m0, mb);
            tma2d(base2 + GSA_L, &mAl, (c + 2) * 64, m0, mb);
            tma2d(base2 + GSB_H, &mBh, (c + 2) * 64, yB, mb);
            tma2d(base2 + GSB_L, &mBl, (c + 2) * 64, yB, mb);
        }
    }

#pragma unroll
    for (int mi = 0; mi < 2; ++mi) {
        int gr = m0 + wr * 32 + mi * 16 + (lane >> 2);
#pragma unroll
        for (int nj = 0; nj < 4; ++nj) {
            int gc = n0 + wc * 32 + nj * 8 + (lane & 3) * 2;
            float2 v0, v1;
            v0.x = acc[mi][nj][0]; v0.y = acc[mi][nj][1];
            v1.x = acc[mi][nj][2]; v1.y = acc[mi][nj][3];
            if (bias) {
                float b0 = bias[gc], b1 = bias[gc + 1];
                v0.x += b0; v0.y += b1; v1.x += b0; v1.y += b1;
            }
            *reinterpret_cast<float2*>(C + (size_t)gr * Ncols + gc) = v0;
            *reinterpret_cast<float2*>(C + (size_t)(gr + 8) * Ncols + gc) = v1;
        }
    }
}

// ---------------- SPD log-projection (merged Q+K) ----------------------------
__global__ __launch_bounds__(256)
void lproj_qk(const float* __restrict__ qkv,
              const float* __restrict__ sq_w, const float* __restrict__ sq_b,
              const float* __restrict__ sk_w, const float* __restrict__ sk_b,
              __nv_bfloat16* __restrict__ lqp, __nv_bfloat16* __restrict__ lkp,
              float* __restrict__ lq2, float* __restrict__ lk2)
{
    __shared__ float s_w[RK][HD];
    __shared__ float s_b[RK];
    __shared__ float s_q[128][HD + 1];

    const int sel  = blockIdx.y;
    const float* src  = qkv + (size_t)sel * MTOT * DIMC;
    const float* w    = sel ? sk_w : sq_w;
    const float* bias = sel ? sk_b : sq_b;
    __nv_bfloat16* lp = sel ? lkp : lqp;
    float* l2arr      = sel ? lk2 : lq2;

    const int bid  = blockIdx.x;
    const int bh   = bid >> 3;
    const int tile = bid & 7;
    const int b    = bh / NH;
    const int h    = bh - b * NH;
    const int tid  = threadIdx.x;

    ((float*)s_w)[tid]       = w[tid & 511];
    ((float*)s_w)[tid + 256] = w[(tid + 256) & 511];
    if (tid < RK) s_b[tid] = bias[tid];

    const float* base = src + ((size_t)(b * SEQ) + tile * 128) * DIMC + h * HD;
#pragma unroll
    for (int u = 0; u < 8; ++u) {
        int s   = tid + u * 256;
        int row = s >> 4;
        int c4  = (s & 15) << 2;
        float4 v = *reinterpret_cast<const float4*>(base + (size_t)row * DIMC + c4);
        s_q[row][c4 + 0] = v.x; s_q[row][c4 + 1] = v.y;
        s_q[row][c4 + 2] = v.z; s_q[row][c4 + 3] = v.w;
    }
    __syncthreads();

    const int token = tid >> 1;
    const int r0    = (tid & 1) * 4;
    float z0 = s_b[r0 + 0], z1 = s_b[r0 + 1], z2 = s_b[r0 + 2], z3 = s_b[r0 + 3];
#pragma unroll
    for (int d = 0; d < HD; ++d) {
        float q = s_q[token][d];
        z0 = fmaf(q, s_w[r0 + 0][d], z0);
        z1 = fmaf(q, s_w[r0 + 1][d], z1);
        z2 = fmaf(q, s_w[r0 + 2][d], z2);
        z3 = fmaf(q, s_w[r0 + 3][d], z3);
    }
    float zz[4] = {z0, z1, z2, z3};
    float hi4[4], lo4[4];
    float s2 = 0.f;
#pragma unroll
    for (int i = 0; i < 4; ++i) {
        float z = zz[i];
        float sp = (z > 20.f) ? z : log1pf(expf(z));
        float l = 0.125f * logf(sp + 1e-6f + 1e-8f);
        s2 = fmaf(l, l, s2);
        float h = __bfloat162float(__float2bfloat16(l));
        hi4[i] = h;
        lo4[i] = l - h;
    }
    s2 += __shfl_xor_sync(0xffffffffu, s2, 1);

    const size_t t = (size_t)bh * SEQ + tile * 128 + token;
    uint2 hp, lq;
    hp.x = pack_bf16x2(hi4[0], hi4[1]);
    hp.y = pack_bf16x2(hi4[2], hi4[3]);
    lq.x = pack_bf16x2(lo4[0], lo4[1]);
    lq.y = pack_bf16x2(lo4[2], lo4[3]);
    *reinterpret_cast<uint2*>(lp + t * 16 + r0)     = hp;
    *reinterpret_cast<uint2*>(lp + t * 16 + 8 + r0) = lq;
    if ((tid & 1) == 0) l2arr[t] = s2;
}

// ---------------- SV precompute ---------------------------------------------
__global__ __launch_bounds__(256)
void svsum_kernel()
{
    __shared__ float part[4][HD];
    const int bh = blockIdx.x;
    const int b = bh / NH, h = bh - b * NH;
    const int tid = threadIdx.x;
    const int d = tid & 63, seg = tid >> 6;
    const float* Vp = g_qkv + (size_t)2 * MTOT * DIMC
                    + (size_t)(b * SEQ) * DIMC + h * HD + d;
    float s = 0.f;
    for (int k = seg * 256; k < seg * 256 + 256; ++k)
        s += Vp[(size_t)k * DIMC];
    part[seg][d] = s;
    __syncthreads();
    if (tid < HD)
        g_sv[bh * HD + tid] = part[0][tid] + part[1][tid]
                            + part[2][tid] + part[3][tid];
}

// ---------------- geodesic attention (validated R9/R10) ----------------------
#define AKT 64
#define UP  72
#define LQP 24

__global__ __launch_bounds__(256, 2)
void attn_mma()
{
    __shared__ __align__(16) __nv_bfloat16 s_lq [128][LQP];
    __shared__ __align__(16) __nv_bfloat16 s_lkA[AKT][LQP];
    __shared__ __align__(16) __nv_bfloat16 s_lkB[AKT][LQP];
    __shared__ float s_lk2[AKT];
    __shared__ float s_sv[HD];
    __shared__ float s_linv[128];
    __shared__ __align__(16) __nv_bfloat16 s_v[AKT][UP];

    const int qb = blockIdx.x, bh = blockIdx.y;
    const int b = bh / NH, h = bh - b * NH;
    const int tid = threadIdx.x, lane = tid & 31, w = tid >> 5;
    const int qq = lane >> 2, ii = lane & 3;
    const int rowq = 16 * w + qq;

    {
        int row = tid >> 1, half = tid & 1;
        *reinterpret_cast<uint4*>(&s_lq[row][half * 8]) =
            *reinterpret_cast<const uint4*>(
                g_lqp + ((size_t)bh * SEQ + qb * 128 + row) * 16 + half * 8);
    }
    if (tid < HD) s_sv[tid] = g_sv[bh * HD + tid];
    const float lq2_0 = g_lq2[(size_t)bh * SEQ + qb * 128 + rowq];
    const float lq2_1 = g_lq2[(size_t)bh * SEQ + qb * 128 + rowq + 8];
    __syncthreads();

    uint32_t aF[4];
    ldsm4(aF, smem_u32(&s_lq[16 * w + (lane & 15)][(lane >> 4) * 8]));

    const float* Vp  = g_qkv + (size_t)2 * MTOT * DIMC
                     + (size_t)(b * SEQ) * DIMC + h * HD;
    const __nv_bfloat16* Lkp = g_lkp + (size_t)bh * SEQ * 16;
    const float* Lk2 = g_lk2 + (size_t)bh * SEQ;

    float acc[8][4];
#pragma unroll
    for (int i = 0; i < 8; i++)
#pragma unroll
        for (int j = 0; j < 4; j++) acc[i][j] = 0.f;
    float us0 = 0.f, us1 = 0.f;

    const int rB = ((lane >> 4) & 1) * 8 + (lane & 7);
    const int cB = ((lane >> 3) & 1) * 8;
    const int rL = lane & 15, cL = (lane >> 4) * 8;

    for (int kt = 0; kt < SEQ / AKT; ++kt) {
        const int key0 = kt * AKT;
        __syncthreads();
        if (tid < 64) {
            uint4 hv = *reinterpret_cast<const uint4*>(Lkp + (key0 + tid) * 16);
            *reinterpret_cast<uint4*>(&s_lkA[tid][0]) = hv;
            *reinterpret_cast<uint4*>(&s_lkA[tid][8]) = hv;
        } else if (tid < 128) {
            int r = tid - 64;
            uint4 lv = *reinterpret_cast<const uint4*>(Lkp + (key0 + r) * 16 + 8);
            *reinterpret_cast<uint4*>(&s_lkB[r][0]) = lv;
            *reinterpret_cast<uint4*>(&s_lkB[r][8]) = make_uint4(0, 0, 0, 0);
        } else if (tid < 192) {
            s_lk2[tid - 128] = Lk2[key0 + tid - 128];
        }
#pragma unroll
        for (int u2 = 0; u2 < 4; ++u2) {
            int s = tid + u2 * 256;
            int key = s >> 4, d4 = (s & 15) * 4;
            float4 v = *(const float4*)(Vp + (size_t)(key0 + key) * DIMC + d4);
            uint2 pk;
            pk.x = pack_bf16x2(v.x, v.y);
            pk.y = pack_bf16x2(v.z, v.w);
            *reinterpret_cast<uint2*>(&s_v[key][d4]) = pk;
        }
        __syncthreads();

        uint32_t uA[4][4];
#pragma unroll
        for (int hhalf = 0; hhalf < 2; ++hhalf) {
            float sacc[4][4];
#pragma unroll
            for (int i = 0; i < 4; i++)
#pragma unroll
                for (int j = 0; j < 4; j++) sacc[i][j] = 0.f;
#pragma unroll
            for (int nj = 0; nj < 2; ++nj) {
                int njj = 2 * hhalf + nj;
                uint32_t addr = (njj * 16 + rB) * (LQP * 2) + cB * 2;
                uint32_t r[4];
                ldsm4(r, smem_u32(s_lkA) + addr);
                uint32_t bb0[2] = {r[0], r[1]};
                uint32_t bb1[2] = {r[2], r[3]};
                uint32_t r2[4];
                ldsm4(r2, smem_u32(s_lkB) + addr);
                uint32_t bc0[2] = {r2[0], r2[1]};
                uint32_t bc1[2] = {r2[2], r2[3]};
                mma16816(sacc[2 * nj],     aF, bb0);
                mma16816(sacc[2 * nj],     aF, bc0);
                mma16816(sacc[2 * nj + 1], aF, bb1);
                mma16816(sacc[2 * nj + 1], aF, bc1);
            }
#pragma unroll
            for (int k = 0; k < 4; ++k) {
                int nc = 4 * hhalf + k;
                int col = 8 * nc + 2 * ii;
                float lk0 = s_lk2[col], lk1 = s_lk2[col + 1];
                float d00 = fmaf(-2.f, sacc[k][0], lq2_0 + lk0);
                float d01 = fmaf(-2.f, sacc[k][1], lq2_0 + lk1);
                float d10 = fmaf(-2.f, sacc[k][2], lq2_1 + lk0);
                float d11 = fmaf(-2.f, sacc[k][3], lq2_1 + lk1);
                d00 = fmaxf(d00, 1.5625e-14f);
                d01 = fmaxf(d01, 1.5625e-14f);
                d10 = fmaxf(d10, 1.5625e-14f);
                d11 = fmaxf(d11, 1.5625e-14f);
                float t00 = sqa(d00), t01 = sqa(d01);
                float t10 = sqa(d10), t11 = sqa(d11);
                const float c2 = -0.5f, c3 = 0.16666667f, c4 = -0.041666667f;
                float u00 = t00 * fmaf(t00, fmaf(t00, fmaf(t00, c4, c3), c2), 1.f);
                float u01 = t01 * fmaf(t01, fmaf(t01, fmaf(t01, c4, c3), c2), 1.f);
                float u10 = t10 * fmaf(t10, fmaf(t10, fmaf(t10, c4, c3), c2), 1.f);
                float u11 = t11 * fmaf(t11, fmaf(t11, fmaf(t11, c4, c3), c2), 1.f);
                us0 += u00 + u01;
                us1 += u10 + u11;
                int kc = nc >> 1;
                if ((nc & 1) == 0) {
                    uA[kc][0] = pack_bf16x2(u00, u01);
                    uA[kc][1] = pack_bf16x2(u10, u11);
                } else {
                    uA[kc][2] = pack_bf16x2(u00, u01);
                    uA[kc][3] = pack_bf16x2(u10, u11);
                }
            }
        }

#pragma unroll
        for (int kc = 0; kc < 4; ++kc) {
#pragma unroll
            for (int vc = 0; vc < 4; ++vc) {
                uint32_t r[4];
                ldsm4t(r, smem_u32(&s_v[16 * kc + rL][16 * vc + cL]));
                mma16816(acc[2 * vc],     uA[kc], r);
                mma16816(acc[2 * vc + 1], uA[kc], r + 2);
            }
        }
    }

    us0 += __shfl_xor_sync(0xffffffffu, us0, 1);
    us0 += __shfl_xor_sync(0xffffffffu, us0, 2);
    us1 += __shfl_xor_sync(0xffffffffu, us1, 1);
    us1 += __shfl_xor_sync(0xffffffffu, us1, 2);
    if (ii == 0) {
        s_linv[rowq]     = 1.f / (1024.f - us0);
        s_linv[rowq + 8] = 1.f / (1024.f - us1);
    }
    __syncthreads();

    const float ilo = s_linv[rowq], ihi = s_linv[rowq + 8];
    const size_t rowb = (size_t)(b * SEQ + qb * 128) * DIMC + h * HD;
#pragma unroll
    for (int nc = 0; nc < 8; ++nc) {
        int c = 8 * nc + ii * 2;
        float sv0 = s_sv[c], sv1 = s_sv[c + 1];
        float o00 = (sv0 - acc[nc][0]) * ilo;
        float o01 = (sv1 - acc[nc][1]) * ilo;
        float o10 = (sv0 - acc[nc][2]) * ihi;
        float o11 = (sv1 - acc[nc][3]) * ihi;
        float h00 = __bfloat162float(__float2bfloat16(o00));
        float h01 = __bfloat162float(__float2bfloat16(o01));
        float h10 = __bfloat162float(__float2bfloat16(o10));
        float h11 = __bfloat162float(__float2bfloat16(o11));
        size_t a0 = rowb + (size_t)rowq * DIMC + c;
        size_t a1 = rowb + (size_t)(rowq + 8) * DIMC + c;
        *reinterpret_cast<uint32_t*>(g_ch + a0) = pack_bf16x2(h00, h01);
        *reinterpret_cast<uint32_t*>(g_cl + a0) = pack_bf16x2(o00 - h00, o01 - h01);
        *reinterpret_cast<uint32_t*>(g_ch + a1) = pack_bf16x2(h10, h11);
        *reinterpret_cast<uint32_t*>(g_cl + a1) = pack_bf16x2(o10 - h10, o11 - h11);
    }
}

// ---------------- KL term (validated: 256-block power-of-two tree) ----------
__global__ __launch_bounds__(256)
void kl_partial(const float* __restrict__ m0, const float* __restrict__ l0,
                const float* __restrict__ m1, const float* __restrict__ l1,
                const float* __restrict__ m2, const float* __restrict__ l2,
                const float* __restrict__ m3, const float* __restrict__ l3)
{
    const int PER4 = PER / 4;
    const int TOT4 = 4 * PER4;
    const float L2E2 = 2.0f * 1.4426950408889634f;
    float s = 0.f;
    for (int i4 = blockIdx.x * blockDim.x + threadIdx.x; i4 < TOT4;
         i4 += gridDim.x * blockDim.x) {
        int p   = i4 / PER4;
        int off = i4 - p * PER4;
        const float* mp = (p == 0) ? m0 : (p == 1) ? m1 : (p == 2) ? m2 : m3;
        const float* lp = (p == 0) ? l0 : (p == 1) ? l1 : (p == 2) ? l2 : l3;
        float4 mu = reinterpret_cast<const float4*>(mp)[off];
        float4 ls = reinterpret_cast<const float4*>(lp)[off];
        s += 0.5f * (ex2a(L2E2 * ls.x) + mu.x * mu.x - 1.f - 2.f * ls.x);
        s += 0.5f * (ex2a(L2E2 * ls.y) + mu.y * mu.y - 1.f - 2.f * ls.y);
        s += 0.5f * (ex2a(L2E2 * ls.z) + mu.z * mu.z - 1.f - 2.f * ls.z);
        s += 0.5f * (ex2a(L2E2 * ls.w) + mu.w * mu.w - 1.f - 2.f * ls.w);
    }
    __shared__ float red[256];
    red[threadIdx.x] = s;
    __syncthreads();
    for (int w = 128; w > 0; w >>= 1) {
        if (threadIdx.x < w) red[threadIdx.x] += red[threadIdx.x + w];
        __syncthreads();
    }
    if (threadIdx.x == 0) g_klpart[blockIdx.x] = red[0];
}

__global__ void kl_final(float* __restrict__ dst)
{
    __shared__ float red[256];
    red[threadIdx.x] = g_klpart[threadIdx.x];
    __syncthreads();
    for (int w = 128; w > 0; w >>= 1) {
        if (threadIdx.x < w) red[threadIdx.x] += red[threadIdx.x + w];
        __syncthreads();
    }
    if (threadIdx.x == 0) *dst = red[0];
}

// ---------------- host: tensor map encoding ---------------------------------
typedef CUresult (*PFN_tmEnc)(CUtensorMap*, CUtensorMapDataType, cuuint32_t,
                              void*, const cuuint64_t*, const cuuint64_t*,
                              const cuuint32_t*, const cuuint32_t*,
                              CUtensorMapInterleave, CUtensorMapSwizzle,
                              CUtensorMapL2promotion, CUtensorMapFloatOOBfill);

static void encode_map(PFN_tmEnc fn, CUtensorMap* m, void* ptr,
                       unsigned long long rows, unsigned boxRows)
{
    cuuint64_t dims[2]    = {(cuuint64_t)KDIM, (cuuint64_t)rows};
    cuuint64_t strides[1] = {(cuuint64_t)KDIM * 2};
    cuuint32_t box[2]     = {64u, boxRows};
    cuuint32_t es[2]      = {1u, 1u};
    fn(m, CU_TENSOR_MAP_DATA_TYPE_BFLOAT16, 2, ptr, dims, strides, box, es,
       CU_TENSOR_MAP_INTERLEAVE_NONE, CU_TENSOR_MAP_SWIZZLE_128B,
       CU_TENSOR_MAP_L2_PROMOTION_L2_128B, CU_TENSOR_MAP_FLOAT_OOB_FILL_NONE);
}

// ---------------- launcher (exact champion graph) ----------------------------
extern "C" void kernel_launch(void* const* d_in, const int* in_sizes, int n_in,
                              void* d_out, int out_size)
{
    const float* x     = (const float*)d_in[0];
    const float* wq_mu = (const float*)d_in[1];
    const float* wq_ls = (const float*)d_in[2];
    const float* wk_mu = (const float*)d_in[3];
    const float* wk_ls = (const float*)d_in[4];
    const float* wv_mu = (const float*)d_in[5];
    const float* wv_ls = (const float*)d_in[6];
    const float* wo_mu = (const float*)d_in[7];
    const float* wo_ls = (const float*)d_in[8];
    const float* wo_b  = (const float*)d_in[9];
    const float* sq_w  = (const float*)d_in[10];
    const float* sq_b  = (const float*)d_in[11];
    const float* sk_w  = (const float*)d_in[12];
    const float* sk_b  = (const float*)d_in[13];
    float* out = (float*)d_out;

    float *qkv_d, *lq2_d, *lk2_d;
    __nv_bfloat16 *lqp_d, *lkp_d;
    __nv_bfloat16 *xh_d, *xl_d, *wh_d, *wl_d, *woh_d, *wol_d, *ch_d, *cl_d;
    cudaGetSymbolAddress((void**)&qkv_d, g_qkv);
    cudaGetSymbolAddress((void**)&lqp_d, g_lqp);
    cudaGetSymbolAddress((void**)&lkp_d, g_lkp);
    cudaGetSymbolAddress((void**)&lq2_d, g_lq2);
    cudaGetSymbolAddress((void**)&lk2_d, g_lk2);
    cudaGetSymbolAddress((void**)&xh_d,  g_xh);
    cudaGetSymbolAddress((void**)&xl_d,  g_xl);
    cudaGetSymbolAddress((void**)&wh_d,  g_wh);
    cudaGetSymbolAddress((void**)&wl_d,  g_wl);
    cudaGetSymbolAddress((void**)&woh_d, g_woh);
    cudaGetSymbolAddress((void**)&wol_d, g_wol);
    cudaGetSymbolAddress((void**)&ch_d,  g_ch);
    cudaGetSymbolAddress((void**)&cl_d,  g_cl);

    static PFN_tmEnc tmEnc = nullptr;
    static cudaStream_t s2 = nullptr;
    static cudaEvent_t evRoot = nullptr, evQKV = nullptr, evSide = nullptr;
    if (!tmEnc) {
        cudaDriverEntryPointQueryResult qr;
        cudaGetDriverEntryPoint("cuTensorMapEncodeTiled", (void**)&tmEnc,
                                cudaEnableDefault, &qr);
        cudaStreamCreateWithFlags(&s2, cudaStreamNonBlocking);
        cudaEventCreateWithFlags(&evRoot, cudaEventDisableTiming);
        cudaEventCreateWithFlags(&evQKV,  cudaEventDisableTiming);
        cudaEventCreateWithFlags(&evSide, cudaEventDisableTiming);
    }
    CUtensorMap mXh, mXl, mWh, mWl, mCh, mCl, mOh, mOl;
    encode_map(tmEnc, &mXh, xh_d,  MTOT,     128);
    encode_map(tmEnc, &mXl, xl_d,  MTOT,     128);
    encode_map(tmEnc, &mWh, wh_d,  3 * DIMC, 64);
    encode_map(tmEnc, &mWl, wl_d,  3 * DIMC, 64);
    encode_map(tmEnc, &mCh, ch_d,  MTOT,     128);
    encode_map(tmEnc, &mCl, cl_d,  MTOT,     128);
    encode_map(tmEnc, &mOh, woh_d, DIMC,     64);
    encode_map(tmEnc, &mOl, wol_d, DIMC,     64);

    cudaFuncSetAttribute(gemm_tma, cudaFuncAttributeMaxDynamicSharedMemorySize,
                         GEMM_DSMEM);

    // fork side stream: KL reduction depends only on inputs
    cudaEventRecord(evRoot, 0);
    cudaStreamWaitEvent(s2, evRoot, 0);
    kl_partial<<<256, 256, 0, s2>>>(wq_mu, wq_ls, wk_mu, wk_ls,
                                    wv_mu, wv_ls, wo_mu, wo_ls);
    if (out_size > MTOT * DIMC) {
        kl_final<<<1, 256, 0, s2>>>(out + (size_t)out_size - 1);
    }

    const int TOTAL4 = MTOT * DIMC / 4 + 4 * (PER / 4);
    split_all<<<TOTAL4 / 512, 256>>>(x, wq_mu, wk_mu, wv_mu, wo_mu, TOTAL4);

    gemm_tma<<<dim3(DIMC / 64, MTOT / 128, 3), 256, GEMM_DSMEM>>>(
        mXh, mXl, mWh, mWl, qkv_d, nullptr, DIMC, (size_t)MTOT * DIMC);
    cudaEventRecord(evQKV, 0);

    // svsum on side stream (depends on V plane of QKV gemm)
    cudaStreamWaitEvent(s2, evQKV, 0);
    svsum_kernel<<<BH, 256, 0, s2>>>();
    cudaEventRecord(evSide, s2);

    // merged Q+K log-projection on main stream
    lproj_qk<<<dim3(BH * 8, 2), 256>>>(qkv_d, sq_w, sq_b, sk_w, sk_b,
                                       lqp_d, lkp_d, lq2_d, lk2_d);

    // join side stream before attention (needs g_sv; also joins KL)
    cudaStreamWaitEvent(0, evSide, 0);

    attn_mma<<<dim3(SEQ / 128, BH), 256>>>();

    gemm_tma<<<dim3(DIMC / 64, MTOT / 128, 1), 256, GEMM_DSMEM>>>(
        mCh, mCl, mOh, mOl, out, wo_b, DIMC, 0);
}